// round 1
// baseline (speedup 1.0000x reference)
#include <cuda_runtime.h>
#include <math.h>

// ---------------------------------------------------------------------------
// Problem constants (fixed shapes per reference)
// ---------------------------------------------------------------------------
#define MAXN 50048
#define MAXE 850048
#define D    128         // D_IN == D_OUT
#define DFF  512
#define NHEAD 8
#define HDIM 16
#define HOPS 5
#define ALPHA 0.15f
#define SLOPE 0.2f
#define LNEPS 1e-5f

// ---------------------------------------------------------------------------
// Scratch (static device globals; no runtime allocation)
// ---------------------------------------------------------------------------
__device__ float d_h   [MAXN * D];
__device__ float d_fh  [MAXN * D];
__device__ float d_ft  [MAXN * D];
__device__ float d_fe  [MAXN * D];
__device__ float d_f0  [MAXN * D];
__device__ float d_f1  [MAXN * D];
__device__ float d_rst [MAXN * D];
__device__ float d_x2  [MAXN * D];
__device__ float d_y1  [MAXN * DFF];
__device__ float d_att [MAXE * NHEAD];
__device__ int   d_csr [MAXE];
__device__ int   d_deg [MAXN];
__device__ int   d_cur [MAXN];
__device__ int   d_row [MAXN + 1];
__device__ float d_log [MAXN];

// ---------------------------------------------------------------------------
// LayerNorm: one warp per row of 128 floats
// ---------------------------------------------------------------------------
__global__ void ln_kernel(const float* __restrict__ x,
                          const float* __restrict__ g,
                          const float* __restrict__ b,
                          float* __restrict__ y, int n)
{
    int warp = (blockIdx.x * blockDim.x + threadIdx.x) >> 5;
    int lane = threadIdx.x & 31;
    if (warp >= n) return;
    const float4 v = *(const float4*)(x + (size_t)warp * D + lane * 4);
    float s  = v.x + v.y + v.z + v.w;
    float ss = v.x*v.x + v.y*v.y + v.z*v.z + v.w*v.w;
    #pragma unroll
    for (int off = 16; off; off >>= 1) {
        s  += __shfl_xor_sync(0xffffffffu, s,  off);
        ss += __shfl_xor_sync(0xffffffffu, ss, off);
    }
    float mean = s * (1.f / D);
    float var  = ss * (1.f / D) - mean * mean;
    float rstd = rsqrtf(var + LNEPS);
    const float4 gv = *(const float4*)(g + lane * 4);
    const float4 bv = *(const float4*)(b + lane * 4);
    float4 o;
    o.x = (v.x - mean) * rstd * gv.x + bv.x;
    o.y = (v.y - mean) * rstd * gv.y + bv.y;
    o.z = (v.z - mean) * rstd * gv.z + bv.z;
    o.w = (v.w - mean) * rstd * gv.w + bv.w;
    *(float4*)(y + (size_t)warp * D + lane * 4) = o;
}

// rst = f + feat; x2 = LN(rst)
__global__ void rst_ln_kernel(const float* __restrict__ f,
                              const float* __restrict__ feat,
                              const float* __restrict__ g,
                              const float* __restrict__ b,
                              float* __restrict__ rst,
                              float* __restrict__ x2, int n)
{
    int warp = (blockIdx.x * blockDim.x + threadIdx.x) >> 5;
    int lane = threadIdx.x & 31;
    if (warp >= n) return;
    const float4 fv = *(const float4*)(f    + (size_t)warp * D + lane * 4);
    const float4 tv = *(const float4*)(feat + (size_t)warp * D + lane * 4);
    float4 r;
    r.x = fv.x + tv.x; r.y = fv.y + tv.y; r.z = fv.z + tv.z; r.w = fv.w + tv.w;
    *(float4*)(rst + (size_t)warp * D + lane * 4) = r;
    float s  = r.x + r.y + r.z + r.w;
    float ss = r.x*r.x + r.y*r.y + r.z*r.z + r.w*r.w;
    #pragma unroll
    for (int off = 16; off; off >>= 1) {
        s  += __shfl_xor_sync(0xffffffffu, s,  off);
        ss += __shfl_xor_sync(0xffffffffu, ss, off);
    }
    float mean = s * (1.f / D);
    float var  = ss * (1.f / D) - mean * mean;
    float rstd = rsqrtf(var + LNEPS);
    const float4 gv = *(const float4*)(g + lane * 4);
    const float4 bv = *(const float4*)(b + lane * 4);
    float4 o;
    o.x = (r.x - mean) * rstd * gv.x + bv.x;
    o.y = (r.y - mean) * rstd * gv.y + bv.y;
    o.z = (r.z - mean) * rstd * gv.z + bv.z;
    o.w = (r.w - mean) * rstd * gv.w + bv.w;
    *(float4*)(x2 + (size_t)warp * D + lane * 4) = o;
}

// ---------------------------------------------------------------------------
// Tiled SGEMM: C[M,Nc] = A[M,K] @ B[Nc,K]^T  (+bias, +add, relu)
// 64x64 tile, BK=16, 256 threads, 4x4 per thread
// ---------------------------------------------------------------------------
template<bool RELU, bool HAS_BIAS, bool HAS_ADD>
__global__ void sgemm_bt_kernel(const float* __restrict__ A,
                                const float* __restrict__ B,
                                const float* __restrict__ bias,
                                const float* __restrict__ add,
                                float* __restrict__ C,
                                int M, int Nc, int K)
{
    const int BM = 64, BN = 64, BK = 16;
    __shared__ float As[BK][BM];
    __shared__ float Bs[BK][BN];
    int tid = threadIdx.x;
    int tx = tid & 15, ty = tid >> 4;
    int m0 = blockIdx.y * BM;
    int n0 = blockIdx.x * BN;
    int lrow  = tid >> 2;          // 0..63
    int lcol4 = (tid & 3) << 2;    // 0,4,8,12

    float acc[4][4] = {};

    for (int k0 = 0; k0 < K; k0 += BK) {
        int ar = m0 + lrow;
        float4 av = (ar < M) ? *(const float4*)(A + (size_t)ar * K + k0 + lcol4)
                             : make_float4(0.f, 0.f, 0.f, 0.f);
        As[lcol4 + 0][lrow] = av.x;
        As[lcol4 + 1][lrow] = av.y;
        As[lcol4 + 2][lrow] = av.z;
        As[lcol4 + 3][lrow] = av.w;
        int br = n0 + lrow;
        float4 bv = (br < Nc) ? *(const float4*)(B + (size_t)br * K + k0 + lcol4)
                              : make_float4(0.f, 0.f, 0.f, 0.f);
        Bs[lcol4 + 0][lrow] = bv.x;
        Bs[lcol4 + 1][lrow] = bv.y;
        Bs[lcol4 + 2][lrow] = bv.z;
        Bs[lcol4 + 3][lrow] = bv.w;
        __syncthreads();
        #pragma unroll
        for (int k = 0; k < BK; k++) {
            float4 a4 = *(const float4*)&As[k][ty * 4];
            float4 b4 = *(const float4*)&Bs[k][tx * 4];
            acc[0][0] += a4.x * b4.x; acc[0][1] += a4.x * b4.y;
            acc[0][2] += a4.x * b4.z; acc[0][3] += a4.x * b4.w;
            acc[1][0] += a4.y * b4.x; acc[1][1] += a4.y * b4.y;
            acc[1][2] += a4.y * b4.z; acc[1][3] += a4.y * b4.w;
            acc[2][0] += a4.z * b4.x; acc[2][1] += a4.z * b4.y;
            acc[2][2] += a4.z * b4.z; acc[2][3] += a4.z * b4.w;
            acc[3][0] += a4.w * b4.x; acc[3][1] += a4.w * b4.y;
            acc[3][2] += a4.w * b4.z; acc[3][3] += a4.w * b4.w;
        }
        __syncthreads();
    }

    int col = n0 + tx * 4;
    float4 biasv = make_float4(0.f, 0.f, 0.f, 0.f);
    if (HAS_BIAS) biasv = *(const float4*)(bias + col);
    #pragma unroll
    for (int i = 0; i < 4; i++) {
        int row = m0 + ty * 4 + i;
        if (row >= M) continue;
        float4 o;
        o.x = acc[i][0] + biasv.x;
        o.y = acc[i][1] + biasv.y;
        o.z = acc[i][2] + biasv.z;
        o.w = acc[i][3] + biasv.w;
        if (RELU) {
            o.x = fmaxf(o.x, 0.f); o.y = fmaxf(o.y, 0.f);
            o.z = fmaxf(o.z, 0.f); o.w = fmaxf(o.w, 0.f);
        }
        if (HAS_ADD) {
            const float4 adv = *(const float4*)(add + (size_t)row * Nc + col);
            o.x += adv.x; o.y += adv.y; o.z += adv.z; o.w += adv.w;
        }
        *(float4*)(C + (size_t)row * Nc + col) = o;
    }
}

// ---------------------------------------------------------------------------
// Graph preprocessing
// ---------------------------------------------------------------------------
__global__ void deg_kernel(const int* __restrict__ dst, int e)
{
    int i = blockIdx.x * blockDim.x + threadIdx.x;
    if (i < e) atomicAdd(&d_deg[dst[i]], 1);
}

__global__ void log_kernel(int n)
{
    int i = blockIdx.x * blockDim.x + threadIdx.x;
    if (i < n) d_log[i] = logf((float)d_deg[i]);
}

// single-block exclusive scan of d_deg -> d_row (1024 threads)
__global__ void scan_kernel(int n)
{
    __shared__ int warpsums[32];
    __shared__ int s_running;
    int tid = threadIdx.x, lane = tid & 31, w = tid >> 5;
    if (tid == 0) s_running = 0;
    __syncthreads();
    for (int base = 0; base < n; base += 1024) {
        int i = base + tid;
        int v = (i < n) ? d_deg[i] : 0;
        int incl = v;
        #pragma unroll
        for (int off = 1; off < 32; off <<= 1) {
            int t = __shfl_up_sync(0xffffffffu, incl, off);
            if (lane >= off) incl += t;
        }
        if (lane == 31) warpsums[w] = incl;
        __syncthreads();
        if (w == 0) {
            int ws = warpsums[lane];
            int wincl = ws;
            #pragma unroll
            for (int off = 1; off < 32; off <<= 1) {
                int t = __shfl_up_sync(0xffffffffu, wincl, off);
                if (lane >= off) wincl += t;
            }
            warpsums[lane] = wincl - ws;  // exclusive warp offset
        }
        __syncthreads();
        int excl = s_running + warpsums[w] + (incl - v);
        if (i < n) d_row[i] = excl;
        __syncthreads();
        if (tid == 1023) s_running = excl + v;
        __syncthreads();
    }
    if (threadIdx.x == 0) d_row[n] = s_running;
}

__global__ void fill_kernel(const int* __restrict__ src,
                            const int* __restrict__ dst, int e)
{
    int i = blockIdx.x * blockDim.x + threadIdx.x;
    if (i >= e) return;
    int dd = dst[i];
    int p = atomicAdd(&d_cur[dd], 1);
    d_csr[d_row[dd] + p] = src[i];
}

// ---------------------------------------------------------------------------
// Attention logits + edge softmax: one warp per destination node.
// Lane l owns dims [4l, 4l+4) -> head = l>>2.
// ---------------------------------------------------------------------------
__global__ void attn_kernel(const float* __restrict__ attnw, int n)
{
    int warp = (blockIdx.x * blockDim.x + threadIdx.x) >> 5;
    int lane = threadIdx.x & 31;
    if (warp >= n) return;
    int node = warp;
    const float4 ftv = *(const float4*)(d_ft + (size_t)node * D + lane * 4);
    const float4 atv = *(const float4*)(attnw + lane * 4);
    float li = d_log[node] * (1.f / HDIM);
    int begin = d_row[node], end = d_row[node + 1];

    float mmax = -1e30f;
    for (int s = begin; s < end; s++) {
        int sn = d_csr[s];
        const float4 fhv = *(const float4*)(d_fh + (size_t)sn * D + lane * 4);
        float p0 = fhv.x * ftv.x; p0 = p0 > 0.f ? p0 : SLOPE * p0;
        float p1 = fhv.y * ftv.y; p1 = p1 > 0.f ? p1 : SLOPE * p1;
        float p2 = fhv.z * ftv.z; p2 = p2 > 0.f ? p2 : SLOPE * p2;
        float p3 = fhv.w * ftv.w; p3 = p3 > 0.f ? p3 : SLOPE * p3;
        float part = p0 * atv.x + p1 * atv.y + p2 * atv.z + p3 * atv.w;
        part += __shfl_xor_sync(0xffffffffu, part, 1);
        part += __shfl_xor_sync(0xffffffffu, part, 2);
        float eh = __shfl_sync(0xffffffffu, part, (lane * 4) & 31) * li;
        if (lane < NHEAD) {
            d_att[(size_t)s * NHEAD + lane] = eh;
            mmax = fmaxf(mmax, eh);
        }
    }
    if (lane < NHEAD) {
        float ssum = 0.f;
        for (int s = begin; s < end; s++) {
            float v = d_att[(size_t)s * NHEAD + lane];
            float ex = expf(v - mmax);
            d_att[(size_t)s * NHEAD + lane] = ex;
            ssum += ex;
        }
        float inv = 1.f / ssum;
        for (int s = begin; s < end; s++)
            d_att[(size_t)s * NHEAD + lane] *= inv;
    }
}

// ---------------------------------------------------------------------------
// One diffusion hop: fout = (1-a)*Agg(fin) + a*fe.  One warp per node.
// ---------------------------------------------------------------------------
__global__ void hop_kernel(const float* __restrict__ fin,
                           float* __restrict__ fout, int n)
{
    int warp = (blockIdx.x * blockDim.x + threadIdx.x) >> 5;
    int lane = threadIdx.x & 31;
    if (warp >= n) return;
    int node = warp;
    int h = lane >> 2;
    int begin = d_row[node], end = d_row[node + 1];
    float4 acc = make_float4(0.f, 0.f, 0.f, 0.f);
    for (int s = begin; s < end; s++) {
        int sn = d_csr[s];
        float av = d_att[(size_t)s * NHEAD + h];
        const float4 fv = *(const float4*)(fin + (size_t)sn * D + lane * 4);
        acc.x += av * fv.x; acc.y += av * fv.y;
        acc.z += av * fv.z; acc.w += av * fv.w;
    }
    const float4 f0v = *(const float4*)(d_fe + (size_t)node * D + lane * 4);
    float4 o;
    o.x = (1.f - ALPHA) * acc.x + ALPHA * f0v.x;
    o.y = (1.f - ALPHA) * acc.y + ALPHA * f0v.y;
    o.z = (1.f - ALPHA) * acc.z + ALPHA * f0v.z;
    o.w = (1.f - ALPHA) * acc.w + ALPHA * f0v.w;
    *(float4*)(fout + (size_t)node * D + lane * 4) = o;
}

// ---------------------------------------------------------------------------
// Host launch
// ---------------------------------------------------------------------------
extern "C" void kernel_launch(void* const* d_in, const int* in_sizes, int n_in,
                              void* d_out, int out_size)
{
    const float* feat  = (const float*)d_in[0];
    const int*   src   = (const int*)  d_in[1];
    const int*   dst   = (const int*)  d_in[2];
    const float* ln1_g = (const float*)d_in[3];
    const float* ln1_b = (const float*)d_in[4];
    const float* W_head= (const float*)d_in[5];
    const float* W_tail= (const float*)d_in[6];
    const float* W_ent = (const float*)d_in[7];
    const float* attnw = (const float*)d_in[8];
    const float* ln2_g = (const float*)d_in[9];
    const float* ln2_b = (const float*)d_in[10];
    const float* W_ff1 = (const float*)d_in[11];
    const float* b_ff1 = (const float*)d_in[12];
    const float* W_ff2 = (const float*)d_in[13];
    const float* b_ff2 = (const float*)d_in[14];

    int n = in_sizes[0] / D;
    int e = in_sizes[1];

    float *p_h, *p_fh, *p_ft, *p_fe, *p_f0, *p_f1, *p_rst, *p_x2, *p_y1;
    int *p_deg, *p_cur;
    cudaGetSymbolAddress((void**)&p_h,  d_h);
    cudaGetSymbolAddress((void**)&p_fh, d_fh);
    cudaGetSymbolAddress((void**)&p_ft, d_ft);
    cudaGetSymbolAddress((void**)&p_fe, d_fe);
    cudaGetSymbolAddress((void**)&p_f0, d_f0);
    cudaGetSymbolAddress((void**)&p_f1, d_f1);
    cudaGetSymbolAddress((void**)&p_rst, d_rst);
    cudaGetSymbolAddress((void**)&p_x2, d_x2);
    cudaGetSymbolAddress((void**)&p_y1, d_y1);
    cudaGetSymbolAddress((void**)&p_deg, d_deg);
    cudaGetSymbolAddress((void**)&p_cur, d_cur);

    cudaMemsetAsync(p_deg, 0, (size_t)n * sizeof(int), 0);
    cudaMemsetAsync(p_cur, 0, (size_t)n * sizeof(int), 0);

    const int TPB = 256;
    int rowBlocks  = (n * 32 + TPB - 1) / TPB;   // warp-per-row kernels
    int edgeBlocks = (e + TPB - 1) / TPB;

    // 1. LN1
    ln_kernel<<<rowBlocks, TPB>>>(feat, ln1_g, ln1_b, p_h, n);

    // 2. projections
    dim3 gproj(D / 64, (n + 63) / 64);
    sgemm_bt_kernel<false, false, false><<<gproj, 256>>>(p_h, W_head, nullptr, nullptr, p_fh, n, D, D);
    sgemm_bt_kernel<false, false, false><<<gproj, 256>>>(p_h, W_tail, nullptr, nullptr, p_ft, n, D, D);
    sgemm_bt_kernel<false, false, false><<<gproj, 256>>>(p_h, W_ent,  nullptr, nullptr, p_fe, n, D, D);

    // 3. CSR build + log-degree
    deg_kernel<<<edgeBlocks, TPB>>>(dst, e);
    scan_kernel<<<1, 1024>>>(n);
    fill_kernel<<<edgeBlocks, TPB>>>(src, dst, e);
    log_kernel<<<(n + TPB - 1) / TPB, TPB>>>(n);

    // 4. attention logits + edge softmax
    attn_kernel<<<rowBlocks, TPB>>>(attnw, n);

    // 5. diffusion: 5 hops, ping-pong (start from fe)
    hop_kernel<<<rowBlocks, TPB>>>(p_fe, p_f1, n);
    hop_kernel<<<rowBlocks, TPB>>>(p_f1, p_f0, n);
    hop_kernel<<<rowBlocks, TPB>>>(p_f0, p_f1, n);
    hop_kernel<<<rowBlocks, TPB>>>(p_f1, p_f0, n);
    hop_kernel<<<rowBlocks, TPB>>>(p_f0, p_f1, n);

    // 6. residual + LN2
    rst_ln_kernel<<<rowBlocks, TPB>>>(p_f1, feat, ln2_g, ln2_b, p_rst, p_x2, n);

    // 7. FFN
    dim3 gff1(DFF / 64, (n + 63) / 64);
    sgemm_bt_kernel<true, true, false><<<gff1, 256>>>(p_x2, W_ff1, b_ff1, nullptr, p_y1, n, DFF, D);
    dim3 gff2(D / 64, (n + 63) / 64);
    sgemm_bt_kernel<false, true, true><<<gff2, 256>>>(p_y1, W_ff2, b_ff2, p_rst, (float*)d_out, n, D, DFF);
}